// round 15
// baseline (speedup 1.0000x reference)
#include <cuda_runtime.h>
#include <stdint.h>

#define HW      49
#define CT      64        // c per CTA
#define CCOLS   512
#define THREADS 256

// Fragment-order smem:
//  Af[4 ks][64 r][4 t] uint4 = (A0hi, A2hi, A0lo, A2lo)        stride 4 uint4/row
//  Bf[4 ks][64 c][5 t-slots] uint4 = (B0hi, B1hi, B0lo, B1lo)  stride 5 (pad) -> conflict-free
#define AF_U4   (4*64*4)               // 1024 uint4 = 16384 B
#define BF_U4   (4*64*5)               // 1280 uint4 = 20480 B
#define OFF_BF  (AF_U4*16)             // byte offset of Bf
#define SMEM_BYTES (AF_U4*16 + BF_U4*16)   // 36864

// pack two f32 -> bf16x2 in ONE instruction (v0 -> lower half, v1 -> upper half)
__device__ __forceinline__ uint32_t packbf2(float v0, float v1) {
    uint32_t r;
    asm("cvt.rn.bf16x2.f32 %0, %1, %2;" : "=r"(r) : "f"(v1), "f"(v0));
    return r;
}

// split pair into packed bf16 (hi-pair, lo-pair); lo = bf16(v - float(bf16(v)))
__device__ __forceinline__ void split_pair(float v0, float v1, uint32_t& hp, uint32_t& lp) {
    hp = packbf2(v0, v1);
    float h0 = __uint_as_float(hp << 16);
    float h1 = __uint_as_float(hp & 0xFFFF0000u);
    lp = packbf2(v0 - h0, v1 - h1);
}

__device__ __forceinline__ void mma16(float* d, uint32_t a0, uint32_t a1, uint32_t a2, uint32_t a3,
                                      uint32_t b0, uint32_t b1) {
    asm volatile(
        "mma.sync.aligned.m16n8k16.row.col.f32.bf16.bf16.f32 "
        "{%0,%1,%2,%3}, {%4,%5,%6,%7}, {%8,%9}, {%0,%1,%2,%3};"
        : "+f"(d[0]), "+f"(d[1]), "+f"(d[2]), "+f"(d[3])
        : "r"(a0), "r"(a1), "r"(a2), "r"(a3), "r"(b0), "r"(b1));
}

__global__ __launch_bounds__(THREADS, 5)
void bmm_bf16_kernel(const float* __restrict__ x,
                     const float* __restrict__ attn,
                     const float* __restrict__ Dm,
                     const float* __restrict__ alpha,
                     float* __restrict__ out)
{
    extern __shared__ __align__(16) char sm[];
    uint4* Af = (uint4*)sm;
    uint4* Bf = (uint4*)(sm + OFF_BF);
    float* Ysh = (float*)Bf;             // Y[c*49+p] (12544 B <= 20480) post-MMA

    const int n   = blockIdx.y;
    const int c0  = blockIdx.x * CT;
    const int tid = threadIdx.x;
    const int wid = tid >> 5;
    const int lid = tid & 31;
    const int g   = lid >> 2;     // groupID
    const int t   = lid & 3;      // thread-in-group

    // ---- stage A = attn[n] in fragment order; rows/q >= 49 zero ----
    // element (ks, r, t): kpairs j0 = 8ks+t (-> A0), j1 = j0+4 (-> A2)
    const float* An = attn + (size_t)n * HW * HW;
    for (int i = tid; i < 64 * 16; i += THREADS) {        // 4 iters
        int r = i >> 4, rem = i & 15;
        int ks = rem >> 2, tt = rem & 3;
        int j0 = 8 * ks + tt;
        float v00 = 0.f, v01 = 0.f, v10 = 0.f, v11 = 0.f;
        if (r < HW) {
            int q = 2 * j0;                               // q, q+1, q+8, q+9
            const float* row = An + r * HW;
            if (q < HW)     v00 = row[q];
            if (q + 1 < HW) v01 = row[q + 1];
            if (q + 8 < HW) v10 = row[q + 8];
            if (q + 9 < HW) v11 = row[q + 9];
        }
        uint32_t hp0, lp0, hp1, lp1;
        split_pair(v00, v01, hp0, lp0);
        split_pair(v10, v11, hp1, lp1);
        Af[(ks * 64 + r) * 4 + tt] = make_uint4(hp0, hp1, lp0, lp1);
    }

    // ---- stage B = D[n][q][c0..c0+63] in fragment order (stride-5 padded) ----
    // element (ks, t, c): kpair rows j0 = 8ks+t, j1 = j0+4
    const float* Dn = Dm + (size_t)n * HW * CCOLS + c0;
    for (int i = tid; i < 16 * 64; i += THREADS) {        // 4 iters
        int rem = i >> 6, c = i & 63;                     // warp-uniform (ks,t)
        int ks = rem >> 2, tt = rem & 3;
        int q = 2 * (8 * ks + tt);
        float v00 = 0.f, v01 = 0.f, v10 = 0.f, v11 = 0.f;
        if (q < HW)     v00 = Dn[(size_t)q * CCOLS + c];
        if (q + 1 < HW) v01 = Dn[(size_t)(q + 1) * CCOLS + c];
        if (q + 8 < HW) v10 = Dn[(size_t)(q + 8) * CCOLS + c];
        if (q + 9 < HW) v11 = Dn[(size_t)(q + 9) * CCOLS + c];
        uint32_t hp0, lp0, hp1, lp1;
        split_pair(v00, v01, hp0, lp0);
        split_pair(v10, v11, hp1, lp1);
        Bf[(ks * 64 + c) * 5 + tt] = make_uint4(hp0, hp1, lp0, lp1);
    }
    __syncthreads();

    // ---- mainloop: warp = (m-tile = wid&3, n-half = wid>>2); 4 k16 steps ----
    const int mb = (wid & 3) * 16;
    const int nb = (wid >> 2) * 32;

    float acc[4][4];
#pragma unroll
    for (int nt = 0; nt < 4; ++nt)
#pragma unroll
        for (int d = 0; d < 4; ++d) acc[nt][d] = 0.f;

    const uint4* aP = Af + (mb + g) * 4 + t;     // A row r=mb+g; +32 for r+8
    const uint4* bP = Bf + (nb + g) * 5 + t;     // B col nb+g; +40 per 8 cols

#pragma unroll
    for (int ks = 0; ks < 4; ++ks) {
        uint4 A0 = aP[ks * 256];                 // (A0hi, A2hi, A0lo, A2lo)
        uint4 A1 = aP[ks * 256 + 32];            // (A1hi, A3hi, A1lo, A3lo)
#pragma unroll
        for (int nt = 0; nt < 4; ++nt) {
            uint4 B = bP[ks * 320 + nt * 40];    // (B0hi, B1hi, B0lo, B1lo)
            mma16(acc[nt], A0.x, A1.x, A0.y, A1.y, B.x, B.y);   // Ah*Bh
            mma16(acc[nt], A0.z, A1.z, A0.w, A1.w, B.x, B.y);   // Al*Bh
            mma16(acc[nt], A0.x, A1.x, A0.y, A1.y, B.z, B.w);   // Ah*Bl
        }
    }

    // ---- prefetch epilogue x (hide DRAM latency behind scatter barriers) ----
    const float  al_  = alpha[0];
    const size_t base = (size_t)n * CCOLS * HW + (size_t)c0 * HW;
    const float4* x4  = (const float4*)(x + base);
    const int i0 = tid, i1 = tid + THREADS, i2 = tid + 2 * THREADS, i3 = tid + 3 * THREADS;
    float4 xp0 = x4[i0];
    float4 xp1 = x4[i1];
    float4 xp2 = x4[i2];
    float4 xp3 = (i3 < (CT * HW) / 4) ? x4[i3] : make_float4(0.f, 0.f, 0.f, 0.f);

    __syncthreads();     // all B reads done — safe to reuse region as Y

    // ---- scatter Y[c][p] into smem for contiguous gmem writes ----
    {
        const int p0 = mb + g, p1 = p0 + 8;
#pragma unroll
        for (int nt = 0; nt < 4; ++nt) {
            const int c = nb + nt * 8 + 2 * t;
            if (p0 < HW) {
                Ysh[c * HW + p0]       = acc[nt][0];
                Ysh[(c + 1) * HW + p0] = acc[nt][1];
            }
            if (p1 < HW) {
                Ysh[c * HW + p1]       = acc[nt][2];
                Ysh[(c + 1) * HW + p1] = acc[nt][3];
            }
        }
    }
    __syncthreads();

    // ---- residual epilogue: out[n, c0:c0+64, :] contiguous (3136 floats) ----
    const float4* y4 = (const float4*)Ysh;
    float4*       o4 = (float4*)(out + base);
    {
        float4 yv, ov;
        yv = y4[i0];
        ov.x = fmaf(al_, yv.x, xp0.x); ov.y = fmaf(al_, yv.y, xp0.y);
        ov.z = fmaf(al_, yv.z, xp0.z); ov.w = fmaf(al_, yv.w, xp0.w);
        o4[i0] = ov;
        yv = y4[i1];
        ov.x = fmaf(al_, yv.x, xp1.x); ov.y = fmaf(al_, yv.y, xp1.y);
        ov.z = fmaf(al_, yv.z, xp1.z); ov.w = fmaf(al_, yv.w, xp1.w);
        o4[i1] = ov;
        yv = y4[i2];
        ov.x = fmaf(al_, yv.x, xp2.x); ov.y = fmaf(al_, yv.y, xp2.y);
        ov.z = fmaf(al_, yv.z, xp2.z); ov.w = fmaf(al_, yv.w, xp2.w);
        o4[i2] = ov;
        if (i3 < (CT * HW) / 4) {
            yv = y4[i3];
            ov.x = fmaf(al_, yv.x, xp3.x); ov.y = fmaf(al_, yv.y, xp3.y);
            ov.z = fmaf(al_, yv.z, xp3.z); ov.w = fmaf(al_, yv.w, xp3.w);
            o4[i3] = ov;
        }
    }
}

extern "C" void kernel_launch(void* const* d_in, const int* in_sizes, int n_in,
                              void* d_out, int out_size)
{
    const float* x     = (const float*)d_in[0];
    const float* attn  = (const float*)d_in[1];
    const float* Dm    = (const float*)d_in[2];
    const float* alpha = (const float*)d_in[3];
    float*       out   = (float*)d_out;

    cudaFuncSetAttribute(bmm_bf16_kernel, cudaFuncAttributeMaxDynamicSharedMemorySize, SMEM_BYTES);

    const int N = in_sizes[1] / (HW * HW);   // 2048
    dim3 grid(CCOLS / CT, N);                // (8, 2048)
    bmm_bf16_kernel<<<grid, THREADS, SMEM_BYTES>>>(x, attn, Dm, alpha, out);
}